// round 1
// baseline (speedup 1.0000x reference)
#include <cuda_runtime.h>
#include <cstdint>

// Shapes (fixed by the problem)
constexpr int N_  = 128;   // MSA depth (s)
constexpr int L_  = 256;   // sequence length
constexpr int DM  = 256;   // d_msa
constexpr int DH  = 32;    // d_hid
constexpr int DP  = 128;   // d_pair
constexpr int RA  = L_ * DH;  // 8192 rows of A / cols of B

// Scratch (device globals: no runtime allocation allowed)
__device__ float g_A[RA * N_];   // A[(l*32+i)][s]   row-major, K(=s) contiguous
__device__ float g_B[N_ * RA];   // B[s][(m*32+j)]   row-major

// ---------------------------------------------------------------------------
// Kernel 1: LayerNorm + left/right projections.
// One warp per (s,l) row. w_left/w_right staged in SMEM as float2 pairs.
// ---------------------------------------------------------------------------
__global__ void __launch_bounds__(256) ln_proj_kernel(
    const float* __restrict__ msa,
    const float* __restrict__ gamma,
    const float* __restrict__ beta,
    const float* __restrict__ wl,
    const float* __restrict__ bleft,
    const float* __restrict__ wr,
    const float* __restrict__ bright)
{
    extern __shared__ float sm1[];
    float2* ws2 = (float2*)sm1;                 // [DM*DH] pairs (left, right)
    float*  xs  = sm1 + DM * DH * 2;            // [8 warps][DM]

    int tid = threadIdx.x;
    for (int e = tid; e < DM * DH; e += 256) {
        int d = e >> 5, k = e & 31;
        ws2[e] = make_float2(wl[d * DH + k], wr[d * DH + k]);
    }
    __syncthreads();

    int warp = tid >> 5, lane = tid & 31;

    for (int rep = 0; rep < 4; rep++) {
        int row = blockIdx.x * 32 + warp * 4 + rep;   // row = s*L + l
        int s = row >> 8;
        int l = row & 255;
        const float* x = msa + (size_t)row * DM;

        float xr[8];
        float sum = 0.f, sq = 0.f;
#pragma unroll
        for (int k2 = 0; k2 < 8; k2++) {
            float v = x[lane + 32 * k2];
            xr[k2] = v;
            sum += v;
            sq  += v * v;
        }
#pragma unroll
        for (int o = 16; o > 0; o >>= 1) {
            sum += __shfl_xor_sync(0xffffffffu, sum, o);
            sq  += __shfl_xor_sync(0xffffffffu, sq, o);
        }
        float mu   = sum * (1.f / DM);
        float var  = sq * (1.f / DM) - mu * mu;
        float rstd = rsqrtf(var + 1e-5f);

#pragma unroll
        for (int k2 = 0; k2 < 8; k2++) {
            int d = lane + 32 * k2;
            xs[warp * DM + d] = (xr[k2] - mu) * rstd * gamma[d] + beta[d];
        }
        __syncwarp();

        float accL = 0.f, accR = 0.f;
#pragma unroll 8
        for (int d = 0; d < DM; d++) {
            float xv = xs[warp * DM + d];
            float2 w = ws2[d * DH + lane];
            accL = fmaf(xv, w.x, accL);
            accR = fmaf(xv, w.y, accR);
        }
        g_A[(size_t)(l * DH + lane) * N_ + s] = accL + bleft[lane];
        g_B[(size_t)s * RA + l * DH + lane]   = (accR + bright[lane]) * (1.f / N_);
        __syncwarp();   // protect xs before next rep overwrites it
    }
}

// ---------------------------------------------------------------------------
// Kernel 2: fused  G = A_tile @ B_tile (128x128, K=128)  then
//           out[pair, p] = sum_ij G * w_out[ij, p]  (+ b_out + pair residual)
// Block tile: 4 l-values x 4 m-values. 256 threads, 8x8 register tile phase A.
// ---------------------------------------------------------------------------
constexpr int SST = 132;   // padded SMEM stride

__global__ void __launch_bounds__(256) fused_kernel(
    const float* __restrict__ pairin,
    const float* __restrict__ wo,
    const float* __restrict__ bo,
    float* __restrict__ outp)
{
    extern __shared__ float sm[];
    float* As = sm;                 // [s][row] transposed, stride SST
    float* Bs = sm + 128 * SST;     // [s][col], stride SST
    float* Gs = sm;                 // reuse As region: [grow][gcol], stride SST
    float* Ws = sm + 128 * SST;     // reuse Bs region: [ij_local][p], stride SST

    int tid = threadIdx.x;
    int bl = blockIdx.x, bm = blockIdx.y;

    // ---- load A (transposed into SMEM) and B tiles ----
#pragma unroll
    for (int it = 0; it < 16; it++) {
        int e4 = tid + 256 * it;
        int flat = e4 << 2;
        int r  = flat >> 7;
        int c0 = flat & 127;
        float4 va = *(const float4*)&g_A[(size_t)(bl * 128 + r) * 128 + c0];
        As[(c0 + 0) * SST + r] = va.x;
        As[(c0 + 1) * SST + r] = va.y;
        As[(c0 + 2) * SST + r] = va.z;
        As[(c0 + 3) * SST + r] = va.w;
        float4 vb = *(const float4*)&g_B[(size_t)r * RA + bm * 128 + c0];
        *(float4*)&Bs[r * SST + c0] = vb;
    }
    __syncthreads();

    // ---- phase A: 128x128 GEMM, K=128, 8x8 per thread ----
    int tx = tid & 15, ty = tid >> 4;
    float acc[8][8];
#pragma unroll
    for (int u = 0; u < 8; u++)
#pragma unroll
        for (int v = 0; v < 8; v++) acc[u][v] = 0.f;

    for (int s = 0; s < 128; s++) {
        float a[8], b[8];
        *(float4*)&a[0] = *(float4*)&As[s * SST + ty * 8];
        *(float4*)&a[4] = *(float4*)&As[s * SST + ty * 8 + 4];
        *(float4*)&b[0] = *(float4*)&Bs[s * SST + tx * 8];
        *(float4*)&b[4] = *(float4*)&Bs[s * SST + tx * 8 + 4];
#pragma unroll
        for (int u = 0; u < 8; u++)
#pragma unroll
            for (int v = 0; v < 8; v++)
                acc[u][v] = fmaf(a[u], b[v], acc[u][v]);
    }
    __syncthreads();   // all As/Bs reads done

    // ---- stash G in SMEM (overwrites As region) ----
#pragma unroll
    for (int u = 0; u < 8; u++) {
        *(float4*)&Gs[(ty * 8 + u) * SST + tx * 8] =
            make_float4(acc[u][0], acc[u][1], acc[u][2], acc[u][3]);
        *(float4*)&Gs[(ty * 8 + u) * SST + tx * 8 + 4] =
            make_float4(acc[u][4], acc[u][5], acc[u][6], acc[u][7]);
    }

    // ---- phase B: out[pair, p] = sum_ij G[l_i, m_j] * W[ij, p] ----
    int pg = tid & 31;   // p = pg*4 .. pg*4+3
    int rg = tid >> 5;   // pairs rg*2, rg*2+1
    float accB[2][4] = {{0.f, 0.f, 0.f, 0.f}, {0.f, 0.f, 0.f, 0.f}};

#pragma unroll 1
    for (int chunk = 0; chunk < 8; chunk++) {
        // stage 128x128 chunk of w_out (overwrites Bs region)
#pragma unroll
        for (int it = 0; it < 16; it++) {
            int e4 = tid + 256 * it;
            int flat = e4 << 2;
            int r  = flat >> 7;
            int c0 = flat & 127;
            *(float4*)&Ws[r * SST + c0] =
                *(const float4*)&wo[(size_t)(chunk * 128 + r) * DP + c0];
        }
        __syncthreads();   // Ws ready (and Gs, on first iter)

#pragma unroll 1
        for (int i2 = 0; i2 < 4; i2++) {
            int i = chunk * 4 + i2;
#pragma unroll
            for (int j = 0; j < 32; j++) {
                int r = i2 * 32 + j;
                float4 w = *(float4*)&Ws[r * SST + pg * 4];
#pragma unroll
                for (int q = 0; q < 2; q++) {
                    int pr = rg * 2 + q;
                    int ll = pr >> 2, mm = pr & 3;
                    float g = Gs[(ll * 32 + i) * SST + mm * 32 + j];
                    accB[q][0] = fmaf(g, w.x, accB[q][0]);
                    accB[q][1] = fmaf(g, w.y, accB[q][1]);
                    accB[q][2] = fmaf(g, w.z, accB[q][2]);
                    accB[q][3] = fmaf(g, w.w, accB[q][3]);
                }
            }
        }
        __syncthreads();   // done reading Ws before next chunk overwrites
    }

    // ---- epilogue: + b_out + pair, write out ----
    float4 bov = *(const float4*)&bo[pg * 4];
#pragma unroll
    for (int q = 0; q < 2; q++) {
        int pr = rg * 2 + q;
        int ll = pr >> 2, mm = pr & 3;
        int l = bl * 4 + ll, m = bm * 4 + mm;
        size_t o = ((size_t)(l * L_ + m)) * DP + pg * 4;
        float4 pv = *(const float4*)&pairin[o];
        float4 res = make_float4(accB[q][0] + bov.x + pv.x,
                                 accB[q][1] + bov.y + pv.y,
                                 accB[q][2] + bov.z + pv.z,
                                 accB[q][3] + bov.w + pv.w);
        *(float4*)&outp[o] = res;
    }
}

// ---------------------------------------------------------------------------
// Launch
// ---------------------------------------------------------------------------
extern "C" void kernel_launch(void* const* d_in, const int* in_sizes, int n_in,
                              void* d_out, int out_size)
{
    const float* msa    = (const float*)d_in[0];
    const float* pairin = (const float*)d_in[1];
    // d_in[2], d_in[3]: symmids/symmsub (int64) — unused by the computation
    const float* gamma  = (const float*)d_in[4];
    const float* beta   = (const float*)d_in[5];
    const float* wl     = (const float*)d_in[6];
    const float* bleft  = (const float*)d_in[7];
    const float* wr     = (const float*)d_in[8];
    const float* bright = (const float*)d_in[9];
    const float* wo     = (const float*)d_in[10];
    const float* bo     = (const float*)d_in[11];
    float* outp = (float*)d_out;

    int smem1 = (DM * DH * 2 + 8 * DM) * sizeof(float);        // 73728 B
    int smem2 = 2 * 128 * SST * sizeof(float);                 // 135168 B
    cudaFuncSetAttribute(ln_proj_kernel,
                         cudaFuncAttributeMaxDynamicSharedMemorySize, smem1);
    cudaFuncSetAttribute(fused_kernel,
                         cudaFuncAttributeMaxDynamicSharedMemorySize, smem2);

    ln_proj_kernel<<<1024, 256, smem1>>>(msa, gamma, beta, wl, bleft, wr, bright);

    dim3 grid(L_ / 4, L_ / 4);   // 64 x 64 blocks
    fused_kernel<<<grid, 256, smem2>>>(pairin, wo, bo, outp);
}

// round 3
// speedup vs baseline: 3.7092x; 3.7092x over previous
#include <cuda_runtime.h>
#include <cstdint>

// Shapes (fixed)
constexpr int N_  = 128;
constexpr int L_  = 256;
constexpr int DM  = 256;
constexpr int DH  = 32;
constexpr int DP  = 128;
constexpr int RA  = L_ * DH;            // 8192
constexpr int NPAIR = L_ * L_;          // 65536

// Device scratch (static; no runtime allocation)
__device__ float g_A[RA * N_];                 // [(l*32+i)][s]  tf32-rounded
__device__ float g_B[RA * N_];                 // [(m*32+j)][s]  tf32-rounded
__device__ float g_Wt[DP * 1024];              // [p][ij]        tf32-rounded
__device__ float g_G[(size_t)NPAIR * 1024];    // [(l,m)][(i,j)] tf32-rounded

// ---------------------------------------------------------------------------
// helpers
// ---------------------------------------------------------------------------
__device__ __forceinline__ uint32_t smem_u32(const void* p) {
    uint32_t a;
    asm("{ .reg .u64 t; cvta.to.shared.u64 t, %1; cvt.u32.u64 %0, t; }"
        : "=r"(a) : "l"(p));
    return a;
}
__device__ __forceinline__ float to_tf32(float x) {
    uint32_t u;
    asm("cvt.rna.tf32.f32 %0, %1;" : "=r"(u) : "f"(x));
    return __uint_as_float(u);
}
__device__ __forceinline__ void ldsm4(uint32_t& r0, uint32_t& r1,
                                      uint32_t& r2, uint32_t& r3, uint32_t a) {
    asm volatile("ldmatrix.sync.aligned.m8n8.x4.shared.b16 {%0,%1,%2,%3}, [%4];"
                 : "=r"(r0), "=r"(r1), "=r"(r2), "=r"(r3) : "r"(a));
}
__device__ __forceinline__ void mma1688(float* d, const uint32_t* a,
                                        uint32_t b0, uint32_t b1) {
    asm volatile(
        "mma.sync.aligned.m16n8k8.row.col.f32.tf32.tf32.f32 "
        "{%0,%1,%2,%3}, {%4,%5,%6,%7}, {%8,%9}, {%0,%1,%2,%3};"
        : "+f"(d[0]), "+f"(d[1]), "+f"(d[2]), "+f"(d[3])
        : "r"(a[0]), "r"(a[1]), "r"(a[2]), "r"(a[3]), "r"(b0), "r"(b1));
}
__device__ __forceinline__ void cpa16(uint32_t dst, const void* src) {
    asm volatile("cp.async.cg.shared.global [%0], [%1], 16;"
                 :: "r"(dst), "l"(src) : "memory");
}
__device__ __forceinline__ void cpa_commit() {
    asm volatile("cp.async.commit_group;" ::: "memory");
}
template <int N>
__device__ __forceinline__ void cpa_wait() {
    asm volatile("cp.async.wait_group %0;" :: "n"(N) : "memory");
}

// ---------------------------------------------------------------------------
// Kernel 1: LayerNorm + left/right projections (tf32-rounded outputs)
// ---------------------------------------------------------------------------
__global__ void __launch_bounds__(256) ln_proj_kernel(
    const float* __restrict__ msa,
    const float* __restrict__ gamma,
    const float* __restrict__ beta,
    const float* __restrict__ wl,
    const float* __restrict__ bleft,
    const float* __restrict__ wr,
    const float* __restrict__ bright)
{
    extern __shared__ float sm1[];
    float2* ws2 = (float2*)sm1;                 // [DM*DH] (left,right) pairs
    float*  xs  = sm1 + DM * DH * 2;            // [8 warps][4 rows][DM]

    int tid = threadIdx.x;
    for (int e = tid; e < DM * DH; e += 256) {
        int d = e >> 5, k = e & 31;
        ws2[e] = make_float2(wl[d * DH + k], wr[d * DH + k]);
    }
    __syncthreads();

    int warp = tid >> 5, lane = tid & 31;
    int row0 = blockIdx.x * 32 + warp * 4;

#pragma unroll
    for (int rep = 0; rep < 4; rep++) {
        const float* x = msa + (size_t)(row0 + rep) * DM;
        float xr[8];
        float sum = 0.f, sq = 0.f;
#pragma unroll
        for (int k2 = 0; k2 < 8; k2++) {
            float v = x[lane + 32 * k2];
            xr[k2] = v; sum += v; sq += v * v;
        }
#pragma unroll
        for (int o = 16; o > 0; o >>= 1) {
            sum += __shfl_xor_sync(0xffffffffu, sum, o);
            sq  += __shfl_xor_sync(0xffffffffu, sq,  o);
        }
        float mu = sum * (1.f / DM);
        float rstd = rsqrtf(sq * (1.f / DM) - mu * mu + 1e-5f);
#pragma unroll
        for (int k2 = 0; k2 < 8; k2++) {
            int d = lane + 32 * k2;
            xs[(warp * 4 + rep) * DM + d] = (xr[k2] - mu) * rstd * gamma[d] + beta[d];
        }
    }
    __syncwarp();

    float aL[4] = {0, 0, 0, 0}, aR[4] = {0, 0, 0, 0};
    const float* xw = xs + warp * 4 * DM;
#pragma unroll 4
    for (int d = 0; d < DM; d++) {
        float2 w = ws2[d * DH + lane];
#pragma unroll
        for (int rep = 0; rep < 4; rep++) {
            float xv = xw[rep * DM + d];
            aL[rep] = fmaf(xv, w.x, aL[rep]);
            aR[rep] = fmaf(xv, w.y, aR[rep]);
        }
    }
    float bl = bleft[lane], br = bright[lane];
#pragma unroll
    for (int rep = 0; rep < 4; rep++) {
        int row = row0 + rep;
        int s = row >> 8, l = row & 255;
        g_A[(size_t)(l * DH + lane) * N_ + s] = to_tf32(aL[rep] + bl);
        g_B[(size_t)(l * DH + lane) * N_ + s] = to_tf32((aR[rep] + br) * (1.f / N_));
    }
}

// ---------------------------------------------------------------------------
// w_out transpose + tf32 round: g_Wt[p][ij]
// ---------------------------------------------------------------------------
__global__ void __launch_bounds__(256) wt_kernel(const float* __restrict__ wo)
{
    int idx = blockIdx.x * 256 + threadIdx.x;     // 131072
    int k = idx >> 7, n = idx & 127;
    g_Wt[(size_t)n * 1024 + k] = to_tf32(wo[idx]);
}

// ---------------------------------------------------------------------------
// GEMM1: G_tile[128x128] = A_tile @ B_tile^T (K=128) via mma.sync tf32.
// 8 warps (2x4), warp tile 64x32, ldmatrix fragments, stride-132 SMEM.
// ---------------------------------------------------------------------------
constexpr int ST1 = 132;

__global__ void __launch_bounds__(256, 1) gemm1_kernel()
{
    extern __shared__ float sm[];
    float* As = sm;                 // [128][ST1]
    float* Bs = sm + 128 * ST1;

    int tid = threadIdx.x, lane = tid & 31, wid = tid >> 5;
    int bl = blockIdx.x, bm = blockIdx.y;

    const float* gA = g_A + (size_t)(bl * 128) * 128;
    const float* gB = g_B + (size_t)(bm * 128) * 128;
#pragma unroll
    for (int it = 0; it < 16; it++) {
        int f4 = it * 256 + tid;
        int row = f4 >> 5, k0 = (f4 & 31) * 4;
        *(float4*)&As[row * ST1 + k0] = *(const float4*)(gA + (size_t)row * 128 + k0);
        *(float4*)&Bs[row * ST1 + k0] = *(const float4*)(gB + (size_t)row * 128 + k0);
    }
    __syncthreads();

    int wm = wid >> 2, wn = wid & 3;
    float acc[4][4][4];
#pragma unroll
    for (int mt = 0; mt < 4; mt++)
#pragma unroll
        for (int nt = 0; nt < 4; nt++)
#pragma unroll
            for (int q = 0; q < 4; q++) acc[mt][nt][q] = 0.f;

    uint32_t sA = smem_u32(As), sB = smem_u32(Bs);
    // ldmatrix per-thread row/col bases
    int aRow = wm * 64 + (lane & 7) + ((lane >> 3) & 1) * 8;
    int aK   = (lane >> 4) * 4;
    int bRow = wn * 32 + (lane & 7) + (lane >> 4) * 8;
    int bK   = ((lane >> 3) & 1) * 4;

#pragma unroll
    for (int ks = 0; ks < 16; ks++) {
        uint32_t a[4][4], b[2][4];
#pragma unroll
        for (int mt = 0; mt < 4; mt++)
            ldsm4(a[mt][0], a[mt][1], a[mt][2], a[mt][3],
                  sA + (uint32_t)(((aRow + mt * 16) * ST1 + aK + ks * 8) * 4));
#pragma unroll
        for (int pr = 0; pr < 2; pr++)
            ldsm4(b[pr][0], b[pr][1], b[pr][2], b[pr][3],
                  sB + (uint32_t)(((bRow + pr * 16) * ST1 + bK + ks * 8) * 4));
#pragma unroll
        for (int mt = 0; mt < 4; mt++)
#pragma unroll
            for (int nt = 0; nt < 4; nt++)
                mma1688(acc[mt][nt], a[mt],
                        b[nt >> 1][(nt & 1) * 2], b[nt >> 1][(nt & 1) * 2 + 1]);
    }

    // epilogue: scatter to g_G[(pair)][(i*32+j)], tf32-rounded
    int r0 = wm * 64 + (lane >> 2);
    int c0 = wn * 32 + (lane & 3) * 2;
#pragma unroll
    for (int mt = 0; mt < 4; mt++) {
        int r = r0 + mt * 16;
        size_t prowBase = ((size_t)(bl * 4 + (r >> 5)) * 256 + bm * 4) * 1024
                        + (size_t)(r & 31) * 32;
#pragma unroll
        for (int nt = 0; nt < 4; nt++) {
            int c = c0 + nt * 8;
            size_t addr = prowBase + (size_t)(c >> 5) * 1024 + (c & 31);
            float2 v0 = make_float2(to_tf32(acc[mt][nt][0]), to_tf32(acc[mt][nt][1]));
            float2 v1 = make_float2(to_tf32(acc[mt][nt][2]), to_tf32(acc[mt][nt][3]));
            *(float2*)&g_G[addr]       = v0;   // row (r),   i = r&31
            *(float2*)&g_G[addr + 256] = v1;   // row (r+8), i+8 -> +8*32
        }
    }
}

// ---------------------------------------------------------------------------
// GEMM2: out[128 pairs x 128] = G[128x1024] @ Wt^T, K in 16 chunks of 64,
// double-buffered cp.async. Epilogue adds b_out + pair.
// ---------------------------------------------------------------------------
constexpr int ST2 = 68;
constexpr int TB2 = 128 * ST2;      // floats per tile buffer

__global__ void __launch_bounds__(256, 1) gemm2_kernel(
    const float* __restrict__ pairin,
    const float* __restrict__ bo,
    float* __restrict__ outp)
{
    extern __shared__ float sm[];
    uint32_t sb = smem_u32(sm);

    int tid = threadIdx.x, lane = tid & 31, wid = tid >> 5;
    int wm = wid >> 2, wn = wid & 3;
    const float* gG = g_G + (size_t)blockIdx.x * 128 * 1024;

    float acc[4][4][4];
#pragma unroll
    for (int mt = 0; mt < 4; mt++)
#pragma unroll
        for (int nt = 0; nt < 4; nt++)
#pragma unroll
            for (int q = 0; q < 4; q++) acc[mt][nt][q] = 0.f;

    int aRow = wm * 64 + (lane & 7) + ((lane >> 3) & 1) * 8;
    int aK   = (lane >> 4) * 4;
    int bRow = wn * 32 + (lane & 7) + (lane >> 4) * 8;
    int bK   = ((lane >> 3) & 1) * 4;

    int ldRow = tid >> 4;             // 0..15  (+16 per it)
    int ldK   = (tid & 15) * 4;

    // prefetch chunk 0 into buffer 0
#pragma unroll
    for (int it = 0; it < 8; it++) {
        int row = ldRow + it * 16;
        uint32_t d = sb + (uint32_t)((row * ST2 + ldK) * 4);
        cpa16(d,            gG   + (size_t)row * 1024 + ldK);
        cpa16(d + TB2 * 4,  g_Wt + (size_t)row * 1024 + ldK);
    }
    cpa_commit();

#pragma unroll 1
    for (int c = 0; c < 16; c++) {
        if (c < 15) {
            uint32_t base = sb + (uint32_t)(((c + 1) & 1) * 2 * TB2 * 4);
#pragma unroll
            for (int it = 0; it < 8; it++) {
                int row = ldRow + it * 16;
                int k = (c + 1) * 64 + ldK;
                uint32_t d = base + (uint32_t)((row * ST2 + ldK) * 4);
                cpa16(d,           gG   + (size_t)row * 1024 + k);
                cpa16(d + TB2 * 4, g_Wt + (size_t)row * 1024 + k);
            }
            cpa_commit();
            cpa_wait<1>();
        } else {
            cpa_wait<0>();
        }
        __syncthreads();

        uint32_t sA = sb + (uint32_t)((c & 1) * 2 * TB2 * 4);
        uint32_t sB = sA + (uint32_t)(TB2 * 4);
#pragma unroll
        for (int ks = 0; ks < 8; ks++) {
            uint32_t a[4][4], b[2][4];
#pragma unroll
            for (int mt = 0; mt < 4; mt++)
                ldsm4(a[mt][0], a[mt][1], a[mt][2], a[mt][3],
                      sA + (uint32_t)(((aRow + mt * 16) * ST2 + aK + ks * 8) * 4));
#pragma unroll
            for (int pr = 0; pr < 2; pr++)
                ldsm4(b[pr][0], b[pr][1], b[pr][2], b[pr][3],
                      sB + (uint32_t)(((bRow + pr * 16) * ST2 + bK + ks * 8) * 4));
#pragma unroll
            for (int mt = 0; mt < 4; mt++)
#pragma unroll
                for (int nt = 0; nt < 4; nt++)
                    mma1688(acc[mt][nt], a[mt],
                            b[nt >> 1][(nt & 1) * 2], b[nt >> 1][(nt & 1) * 2 + 1]);
        }
        __syncthreads();
    }

    // epilogue: + b_out + pair
    int r0 = wm * 64 + (lane >> 2);
    int c0 = wn * 32 + (lane & 3) * 2;
    size_t pairBase = (size_t)blockIdx.x * 128;
#pragma unroll
    for (int mt = 0; mt < 4; mt++) {
        int r = r0 + mt * 16;
#pragma unroll
        for (int nt = 0; nt < 4; nt++) {
            int c = c0 + nt * 8;
            float2 b2 = *(const float2*)&bo[c];
            size_t i0 = (pairBase + r) * 128 + c;
            size_t i1 = i0 + (size_t)8 * 128;
            float2 p0 = *(const float2*)&pairin[i0];
            float2 p1 = *(const float2*)&pairin[i1];
            float2 o0 = make_float2(acc[mt][nt][0] + b2.x + p0.x,
                                    acc[mt][nt][1] + b2.y + p0.y);
            float2 o1 = make_float2(acc[mt][nt][2] + b2.x + p1.x,
                                    acc[mt][nt][3] + b2.y + p1.y);
            *(float2*)&outp[i0] = o0;
            *(float2*)&outp[i1] = o1;
        }
    }
}

// ---------------------------------------------------------------------------
// Launch
// ---------------------------------------------------------------------------
extern "C" void kernel_launch(void* const* d_in, const int* in_sizes, int n_in,
                              void* d_out, int out_size)
{
    const float* msa    = (const float*)d_in[0];
    const float* pairin = (const float*)d_in[1];
    const float* gamma  = (const float*)d_in[4];
    const float* beta   = (const float*)d_in[5];
    const float* wl     = (const float*)d_in[6];
    const float* bleft  = (const float*)d_in[7];
    const float* wr     = (const float*)d_in[8];
    const float* bright = (const float*)d_in[9];
    const float* wo     = (const float*)d_in[10];
    const float* bo     = (const float*)d_in[11];
    float* outp = (float*)d_out;

    int smem1 = (DM * DH * 2 + 8 * 4 * DM) * (int)sizeof(float);  // 98304
    int smemA = 2 * 128 * ST1 * (int)sizeof(float);               // 135168
    int smemB = 4 * TB2 * (int)sizeof(float);                     // 139264
    cudaFuncSetAttribute(ln_proj_kernel,
                         cudaFuncAttributeMaxDynamicSharedMemorySize, smem1);
    cudaFuncSetAttribute(gemm1_kernel,
                         cudaFuncAttributeMaxDynamicSharedMemorySize, smemA);
    cudaFuncSetAttribute(gemm2_kernel,
                         cudaFuncAttributeMaxDynamicSharedMemorySize, smemB);

    ln_proj_kernel<<<1024, 256, smem1>>>(msa, gamma, beta, wl, bleft, wr, bright);
    wt_kernel<<<512, 256>>>(wo);
    gemm1_kernel<<<dim3(64, 64), 256, smemA>>>();
    gemm2_kernel<<<512, 256, smemB>>>(pairin, bo, outp);
}

// round 4
// speedup vs baseline: 3.9229x; 1.0576x over previous
#include <cuda_runtime.h>
#include <cstdint>

// Shapes (fixed)
constexpr int N_  = 128;
constexpr int L_  = 256;
constexpr int DM  = 256;
constexpr int DH  = 32;
constexpr int DP  = 128;
constexpr int RA  = L_ * DH;            // 8192

// Device scratch
__device__ float g_A[RA * N_];    // [(l*32+i)][s]  tf32-rounded
__device__ float g_B[RA * N_];    // [(m*32+j)][s]  tf32-rounded
__device__ float g_Wt[DP * 1024]; // [n][ij]        tf32-rounded

// ---------------------------------------------------------------------------
// helpers
// ---------------------------------------------------------------------------
__device__ __forceinline__ uint32_t smem_u32(const void* p) {
    uint32_t a;
    asm("{ .reg .u64 t; cvta.to.shared.u64 t, %1; cvt.u32.u64 %0, t; }"
        : "=r"(a) : "l"(p));
    return a;
}
__device__ __forceinline__ float to_tf32(float x) {
    uint32_t u;
    asm("cvt.rna.tf32.f32 %0, %1;" : "=r"(u) : "f"(x));
    return __uint_as_float(u);
}
__device__ __forceinline__ void ldsm4(uint32_t& r0, uint32_t& r1,
                                      uint32_t& r2, uint32_t& r3, uint32_t a) {
    asm volatile("ldmatrix.sync.aligned.m8n8.x4.shared.b16 {%0,%1,%2,%3}, [%4];"
                 : "=r"(r0), "=r"(r1), "=r"(r2), "=r"(r3) : "r"(a));
}
__device__ __forceinline__ void mma1688(float* d, const uint32_t* a,
                                        uint32_t b0, uint32_t b1) {
    asm volatile(
        "mma.sync.aligned.m16n8k8.row.col.f32.tf32.tf32.f32 "
        "{%0,%1,%2,%3}, {%4,%5,%6,%7}, {%8,%9}, {%0,%1,%2,%3};"
        : "+f"(d[0]), "+f"(d[1]), "+f"(d[2]), "+f"(d[3])
        : "r"(a[0]), "r"(a[1]), "r"(a[2]), "r"(a[3]), "r"(b0), "r"(b1));
}
__device__ __forceinline__ void cpa16(uint32_t dst, const void* src) {
    asm volatile("cp.async.cg.shared.global [%0], [%1], 16;"
                 :: "r"(dst), "l"(src) : "memory");
}
__device__ __forceinline__ void cpa_commit() {
    asm volatile("cp.async.commit_group;" ::: "memory");
}
template <int N>
__device__ __forceinline__ void cpa_wait() {
    asm volatile("cp.async.wait_group %0;" :: "n"(N) : "memory");
}

// ---------------------------------------------------------------------------
// Kernel 1: LayerNorm + left/right projections (tf32-rounded outputs)
// ---------------------------------------------------------------------------
__global__ void __launch_bounds__(256) ln_proj_kernel(
    const float* __restrict__ msa,
    const float* __restrict__ gamma,
    const float* __restrict__ beta,
    const float* __restrict__ wl,
    const float* __restrict__ bleft,
    const float* __restrict__ wr,
    const float* __restrict__ bright)
{
    extern __shared__ float sm1[];
    float2* ws2 = (float2*)sm1;
    float*  xs  = sm1 + DM * DH * 2;

    int tid = threadIdx.x;
    for (int e = tid; e < DM * DH; e += 256) {
        int d = e >> 5, k = e & 31;
        ws2[e] = make_float2(wl[d * DH + k], wr[d * DH + k]);
    }
    __syncthreads();

    int warp = tid >> 5, lane = tid & 31;
    int row0 = blockIdx.x * 32 + warp * 4;

#pragma unroll
    for (int rep = 0; rep < 4; rep++) {
        const float* x = msa + (size_t)(row0 + rep) * DM;
        float xr[8];
        float sum = 0.f, sq = 0.f;
#pragma unroll
        for (int k2 = 0; k2 < 8; k2++) {
            float v = x[lane + 32 * k2];
            xr[k2] = v; sum += v; sq += v * v;
        }
#pragma unroll
        for (int o = 16; o > 0; o >>= 1) {
            sum += __shfl_xor_sync(0xffffffffu, sum, o);
            sq  += __shfl_xor_sync(0xffffffffu, sq,  o);
        }
        float mu = sum * (1.f / DM);
        float rstd = rsqrtf(sq * (1.f / DM) - mu * mu + 1e-5f);
#pragma unroll
        for (int k2 = 0; k2 < 8; k2++) {
            int d = lane + 32 * k2;
            xs[(warp * 4 + rep) * DM + d] = (xr[k2] - mu) * rstd * gamma[d] + beta[d];
        }
    }
    __syncwarp();

    float aL[4] = {0, 0, 0, 0}, aR[4] = {0, 0, 0, 0};
    const float* xw = xs + warp * 4 * DM;
#pragma unroll 4
    for (int d = 0; d < DM; d++) {
        float2 w = ws2[d * DH + lane];
#pragma unroll
        for (int rep = 0; rep < 4; rep++) {
            float xv = xw[rep * DM + d];
            aL[rep] = fmaf(xv, w.x, aL[rep]);
            aR[rep] = fmaf(xv, w.y, aR[rep]);
        }
    }
    float bl = bleft[lane], br = bright[lane];
#pragma unroll
    for (int rep = 0; rep < 4; rep++) {
        int row = row0 + rep;
        int s = row >> 8, l = row & 255;
        g_A[(size_t)(l * DH + lane) * N_ + s] = to_tf32(aL[rep] + bl);
        g_B[(size_t)(l * DH + lane) * N_ + s] = to_tf32((aR[rep] + br) * (1.f / N_));
    }
}

// ---------------------------------------------------------------------------
// w_out transpose + tf32 round: g_Wt[n][ij]
// ---------------------------------------------------------------------------
__global__ void __launch_bounds__(256) wt_kernel(const float* __restrict__ wo)
{
    int idx = blockIdx.x * 256 + threadIdx.x;
    int k = idx >> 7, n = idx & 127;
    g_Wt[(size_t)n * 1024 + k] = to_tf32(wo[idx]);
}

// ---------------------------------------------------------------------------
// Fused GEMM: per CTA, 8 l x 8 m = 64 pairs.
//   For each i-chunk (4 i's): Gc[32 x 256] = A_sub @ B^T  ->  Gs[64 pr][128 ij]
//   then out[64][128] += Gs @ Wchunk (K=128 ij), W double-buffered cp.async.
// Epilogue restages out via SMEM for coalesced writes (+ b_out + pair).
// ---------------------------------------------------------------------------
// SMEM float offsets
constexpr int B_OFF = 0;                       // [256][132]
constexpr int A_OFF = B_OFF + 256 * 132;       // [32][132]
constexpr int G_OFF = A_OFF + 32 * 132;        // [64][132]
constexpr int W_OFF = G_OFF + 64 * 132;        // 2 x [128][36]
constexpr int WBUF  = 128 * 36;
constexpr int SMEM_FUSED = (W_OFF + 2 * WBUF) * 4;   // 222720 bytes

__global__ void __launch_bounds__(256, 1) fused_gemm_kernel(
    const float* __restrict__ pairin,
    const float* __restrict__ bo,
    float* __restrict__ outp)
{
    extern __shared__ float sm[];
    uint32_t sb = smem_u32(sm);
    int tid = threadIdx.x, lane = tid & 31, w = tid >> 5;
    int bl = blockIdx.x, bm = blockIdx.y;

    // ---- W prefetch thread mapping: 128 rows x 8 x 16B per sub-chunk ----
    int wRow = 0, wSeg = 0;
    {
        int f = tid;         // thread does segs f, f+256, ... (4 total)
        wRow = f >> 3; wSeg = f & 7;
    }
    auto prefetchW = [&](int t) {
        int ic = t >> 2, wsub = t & 3;
        int koff = ic * 128 + wsub * 32;
        uint32_t base = sb + (uint32_t)((W_OFF + (t & 1) * WBUF) * 4);
#pragma unroll
        for (int it = 0; it < 4; it++) {
            int row = wRow + it * 32;
            cpa16(base + (uint32_t)((row * 36 + wSeg * 4) * 4),
                  g_Wt + (size_t)row * 1024 + koff + wSeg * 4);
        }
        cpa_commit();
    };

    prefetchW(0);
    prefetchW(1);

    // ---- load B tile: rows bm*256 .. +256, contiguous ----
    const float* gB = g_B + (size_t)(bm * 256) * 128;
#pragma unroll
    for (int it = 0; it < 32; it++) {
        int f = it * 256 + tid;
        int r = f >> 5, c4 = (f & 31) * 4;
        *(float4*)&sm[B_OFF + r * 132 + c4] = *(const float4*)(gB + (size_t)r * 128 + c4);
    }

    // ldmatrix bases
    int aRowA = (lane & 7) + ((lane >> 3) & 1) * 8;   // + mt*16
    int aKA   = (lane >> 4) * 4;
    int bRowA = w * 32 + (lane & 7) + (lane >> 4) * 8; // + pr*16
    int bKA   = ((lane >> 3) & 1) * 4;

    int aRowB = (lane & 7) + ((lane >> 3) & 1) * 8;   // + mt2*16 (over pairs)
    int aKB   = (lane >> 4) * 4;
    int bRowB = w * 16 + (lane & 7) + (lane >> 4) * 8; // over n (16 per warp)
    int bKB   = ((lane >> 3) & 1) * 4;

    uint32_t sA = sb + (uint32_t)(A_OFF * 4);
    uint32_t sBt = sb + (uint32_t)(B_OFF * 4);
    uint32_t sG = sb + (uint32_t)(G_OFF * 4);

    float outAcc[4][2][4];
#pragma unroll
    for (int mt = 0; mt < 4; mt++)
#pragma unroll
        for (int nt = 0; nt < 2; nt++)
#pragma unroll
            for (int q = 0; q < 4; q++) outAcc[mt][nt][q] = 0.f;

#pragma unroll 1
    for (int ic = 0; ic < 8; ic++) {
        __syncthreads();   // previous phase-B reads of Gs done; As free

        // ---- load A chunk: 32 rows (l_loc, di) ----
        const float* gA = g_A + (size_t)(bl * 256) * 128;
#pragma unroll
        for (int it = 0; it < 4; it++) {
            int f = it * 256 + tid;
            int r = f >> 5, c4 = (f & 31) * 4;
            int grow = (r >> 2) * 32 + ic * 4 + (r & 3);
            *(float4*)&sm[A_OFF + r * 132 + c4] =
                *(const float4*)(gA + (size_t)grow * 128 + c4);
        }
        __syncthreads();   // A (and B on first iter) visible

        // ---- phase A: Gc[32 x 256] = A @ B^T, K=128 ----
        float accA[2][4][4];
#pragma unroll
        for (int mt = 0; mt < 2; mt++)
#pragma unroll
            for (int nt = 0; nt < 4; nt++)
#pragma unroll
                for (int q = 0; q < 4; q++) accA[mt][nt][q] = 0.f;

#pragma unroll
        for (int ks = 0; ks < 16; ks++) {
            uint32_t a[2][4], b[2][4];
#pragma unroll
            for (int mt = 0; mt < 2; mt++)
                ldsm4(a[mt][0], a[mt][1], a[mt][2], a[mt][3],
                      sA + (uint32_t)((((aRowA + mt * 16) * 132) + aKA + ks * 8) * 4));
#pragma unroll
            for (int pr = 0; pr < 2; pr++)
                ldsm4(b[pr][0], b[pr][1], b[pr][2], b[pr][3],
                      sBt + (uint32_t)((((bRowA + pr * 16) * 132) + bKA + ks * 8) * 4));
#pragma unroll
            for (int mt = 0; mt < 2; mt++)
#pragma unroll
                for (int nt = 0; nt < 4; nt++)
                    mma1688(accA[mt][nt], a[mt],
                            b[nt >> 1][(nt & 1) * 2], b[nt >> 1][(nt & 1) * 2 + 1]);
        }

        // ---- store Gc fragments into Gs[pair][ij_local] ----
        {
            int rB = lane >> 2;            // 0..7
            int jB = (lane & 3) * 2;
#pragma unroll
            for (int mt = 0; mt < 2; mt++) {
                int r = mt * 16 + rB;      // 0..23
#pragma unroll
                for (int nt = 0; nt < 4; nt++) {
                    int q = (r & 3) * 32 + nt * 8 + jB;
                    int p = (r >> 2) * 8 + w;
                    *(float2*)&sm[G_OFF + p * 132 + q] =
                        make_float2(accA[mt][nt][0], accA[mt][nt][1]);
                    *(float2*)&sm[G_OFF + (p + 16) * 132 + q] =
                        make_float2(accA[mt][nt][2], accA[mt][nt][3]);
                }
            }
        }
        __syncthreads();   // Gs visible

        // ---- phase B: out += Gs[64x128] @ W[128x128] (4 sub-K of 32) ----
#pragma unroll 1
        for (int wsub = 0; wsub < 4; wsub++) {
            int t = ic * 4 + wsub;
            cpa_wait<1>();
            __syncthreads();   // W buffer (t&1) visible to all warps
            uint32_t sW = sb + (uint32_t)((W_OFF + (t & 1) * WBUF) * 4);
#pragma unroll
            for (int ks2 = 0; ks2 < 4; ks2++) {
                uint32_t a[4][4], b[4];
#pragma unroll
                for (int mt = 0; mt < 4; mt++)
                    ldsm4(a[mt][0], a[mt][1], a[mt][2], a[mt][3],
                          sG + (uint32_t)((((aRowB + mt * 16) * 132)
                               + aKB + wsub * 32 + ks2 * 8) * 4));
                ldsm4(b[0], b[1], b[2], b[3],
                      sW + (uint32_t)(((bRowB * 36) + bKB + ks2 * 8) * 4));
#pragma unroll
                for (int mt = 0; mt < 4; mt++) {
                    mma1688(outAcc[mt][0], a[mt], b[0], b[1]);
                    mma1688(outAcc[mt][1], a[mt], b[2], b[3]);
                }
            }
            __syncthreads();   // done reading W buffer before overwrite
            if (t + 2 < 32) prefetchW(t + 2);
        }
    }
    __syncthreads();   // all phase-B reads of Gs done

    // ---- epilogue: restage out through Gs for coalesced writes ----
    {
        int rB = lane >> 2;
        int nB = (lane & 3) * 2;
#pragma unroll
        for (int mt = 0; mt < 4; mt++) {
            int p = mt * 16 + rB;
#pragma unroll
            for (int nt = 0; nt < 2; nt++) {
                int nc = w * 16 + nt * 8 + nB;
                *(float2*)&sm[G_OFF + p * 132 + nc] =
                    make_float2(outAcc[mt][nt][0], outAcc[mt][nt][1]);
                *(float2*)&sm[G_OFF + (p + 8) * 132 + nc] =
                    make_float2(outAcc[mt][nt][2], outAcc[mt][nt][3]);
            }
        }
    }
    __syncthreads();

#pragma unroll
    for (int it = 0; it < 8; it++) {
        int f = it * 256 + tid;          // 2048 float4
        int p = f >> 5;                  // pair local 0..63
        int c4 = (f & 31) * 4;
        int l = bl * 8 + (p >> 3);
        int m = bm * 8 + (p & 7);
        size_t o = ((size_t)(l * L_ + m)) * DP + c4;
        float4 v = *(float4*)&sm[G_OFF + p * 132 + c4];
        float4 pv = *(const float4*)&pairin[o];
        float4 bv = *(const float4*)&bo[c4];
        v.x += pv.x + bv.x; v.y += pv.y + bv.y;
        v.z += pv.z + bv.z; v.w += pv.w + bv.w;
        *(float4*)&outp[o] = v;
    }
}

// ---------------------------------------------------------------------------
// Launch
// ---------------------------------------------------------------------------
extern "C" void kernel_launch(void* const* d_in, const int* in_sizes, int n_in,
                              void* d_out, int out_size)
{
    const float* msa    = (const float*)d_in[0];
    const float* pairin = (const float*)d_in[1];
    const float* gamma  = (const float*)d_in[4];
    const float* beta   = (const float*)d_in[5];
    const float* wl     = (const float*)d_in[6];
    const float* bleft  = (const float*)d_in[7];
    const float* wr     = (const float*)d_in[8];
    const float* bright = (const float*)d_in[9];
    const float* wo     = (const float*)d_in[10];
    const float* bo     = (const float*)d_in[11];
    float* outp = (float*)d_out;

    int smem1 = (DM * DH * 2 + 8 * 4 * DM) * (int)sizeof(float);
    cudaFuncSetAttribute(ln_proj_kernel,
                         cudaFuncAttributeMaxDynamicSharedMemorySize, smem1);
    cudaFuncSetAttribute(fused_gemm_kernel,
                         cudaFuncAttributeMaxDynamicSharedMemorySize, SMEM_FUSED);

    ln_proj_kernel<<<1024, 256, smem1>>>(msa, gamma, beta, wl, bleft, wr, bright);
    wt_kernel<<<512, 256>>>(wo);
    fused_gemm_kernel<<<dim3(32, 32), 256, SMEM_FUSED>>>(pairin, bo, outp);
}

// round 5
// speedup vs baseline: 4.6663x; 1.1895x over previous
#include <cuda_runtime.h>
#include <cuda_fp16.h>
#include <cstdint>

// Shapes (fixed)
constexpr int N_  = 128;
constexpr int L_  = 256;
constexpr int DM  = 256;
constexpr int DH  = 32;
constexpr int DP  = 128;
constexpr int RA  = L_ * DH;            // 8192

// Device scratch (fp16)
__device__ __half g_A[RA * N_];     // [(l*32+i)][s]
__device__ __half g_B[RA * N_];     // [(m*32+j)][s]
__device__ __half g_Wt[DP * 1024];  // [n][ij]

// ---------------------------------------------------------------------------
// helpers
// ---------------------------------------------------------------------------
__device__ __forceinline__ uint32_t smem_u32(const void* p) {
    uint32_t a;
    asm("{ .reg .u64 t; cvta.to.shared.u64 t, %1; cvt.u32.u64 %0, t; }"
        : "=r"(a) : "l"(p));
    return a;
}
__device__ __forceinline__ void ldsm4(uint32_t& r0, uint32_t& r1,
                                      uint32_t& r2, uint32_t& r3, uint32_t a) {
    asm volatile("ldmatrix.sync.aligned.m8n8.x4.shared.b16 {%0,%1,%2,%3}, [%4];"
                 : "=r"(r0), "=r"(r1), "=r"(r2), "=r"(r3) : "r"(a));
}
__device__ __forceinline__ void mma16816(float* d, const uint32_t* a,
                                         uint32_t b0, uint32_t b1) {
    asm volatile(
        "mma.sync.aligned.m16n8k16.row.col.f32.f16.f16.f32 "
        "{%0,%1,%2,%3}, {%4,%5,%6,%7}, {%8,%9}, {%0,%1,%2,%3};"
        : "+f"(d[0]), "+f"(d[1]), "+f"(d[2]), "+f"(d[3])
        : "r"(a[0]), "r"(a[1]), "r"(a[2]), "r"(a[3]), "r"(b0), "r"(b1));
}
__device__ __forceinline__ void cpa16(uint32_t dst, const void* src) {
    asm volatile("cp.async.cg.shared.global [%0], [%1], 16;"
                 :: "r"(dst), "l"(src) : "memory");
}
__device__ __forceinline__ void cpa_commit() {
    asm volatile("cp.async.commit_group;" ::: "memory");
}
template <int N>
__device__ __forceinline__ void cpa_wait() {
    asm volatile("cp.async.wait_group %0;" :: "n"(N) : "memory");
}

// ---------------------------------------------------------------------------
// Kernel 1: LayerNorm + projections. Block = (l, s-chunk of 32).
// Transposed padded weights in SMEM (conflict-free float4), fp16 outputs
// transposed through SMEM for coalesced stores.
// ---------------------------------------------------------------------------
constexpr int WST = 260;

__global__ void __launch_bounds__(256) ln_proj_kernel(
    const float* __restrict__ msa,
    const float* __restrict__ gamma,
    const float* __restrict__ beta,
    const float* __restrict__ wl,
    const float* __restrict__ bleft,
    const float* __restrict__ wr,
    const float* __restrict__ bright)
{
    extern __shared__ float sm1[];
    float* wlT = sm1;                  // [32][260]
    float* wrT = sm1 + 32 * WST;       // [32][260]
    float* xs  = sm1 + 64 * WST;       // [32][256]; reused as tA/tB stage

    int tid = threadIdx.x;
    int l  = blockIdx.x >> 2;
    int sc = blockIdx.x & 3;

    for (int e = tid; e < 32 * 256; e += 256) {
        int k = e >> 8, d = e & 255;
        wlT[k * WST + d] = wl[d * 32 + k];
        wrT[k * WST + d] = wr[d * 32 + k];
    }
    __syncthreads();

    int warp = tid >> 5, lane = tid & 31;

    // LN: 4 rows per warp, s = sc*32 + warp*4 + rep
#pragma unroll
    for (int rep = 0; rep < 4; rep++) {
        int s = sc * 32 + warp * 4 + rep;
        const float* x = msa + ((size_t)s * L_ + l) * DM;
        float xr[8];
        float sum = 0.f, sq = 0.f;
#pragma unroll
        for (int k2 = 0; k2 < 8; k2++) {
            float v = x[lane + 32 * k2];
            xr[k2] = v; sum += v; sq += v * v;
        }
#pragma unroll
        for (int o = 16; o > 0; o >>= 1) {
            sum += __shfl_xor_sync(0xffffffffu, sum, o);
            sq  += __shfl_xor_sync(0xffffffffu, sq,  o);
        }
        float mu = sum * (1.f / DM);
        float rstd = rsqrtf(sq * (1.f / DM) - mu * mu + 1e-5f);
#pragma unroll
        for (int k2 = 0; k2 < 8; k2++) {
            int d = lane + 32 * k2;
            xs[(warp * 4 + rep) * 256 + d] = (xr[k2] - mu) * rstd * gamma[d] + beta[d];
        }
    }
    __syncwarp();

    float aL[4] = {0, 0, 0, 0}, aR[4] = {0, 0, 0, 0};
    const float* xw = xs + warp * 4 * 256;
#pragma unroll 2
    for (int d4 = 0; d4 < 64; d4++) {
        float4 w1 = *(float4*)&wlT[lane * WST + d4 * 4];
        float4 w2 = *(float4*)&wrT[lane * WST + d4 * 4];
#pragma unroll
        for (int rep = 0; rep < 4; rep++) {
            float4 x4 = *(float4*)&xw[rep * 256 + d4 * 4];
            aL[rep] = fmaf(x4.x, w1.x, fmaf(x4.y, w1.y,
                      fmaf(x4.z, w1.z, fmaf(x4.w, w1.w, aL[rep]))));
            aR[rep] = fmaf(x4.x, w2.x, fmaf(x4.y, w2.y,
                      fmaf(x4.z, w2.z, fmaf(x4.w, w2.w, aR[rep]))));
        }
    }
    float blv = bleft[lane], brv = bright[lane];
    __syncthreads();   // all xs reads done before reuse as stage

    float* tA = xs;                 // [32][33]
    float* tB = xs + 32 * 33;       // [32][33]
#pragma unroll
    for (int rep = 0; rep < 4; rep++) {
        int sl = warp * 4 + rep;
        tA[sl * 33 + lane] = aL[rep] + blv;
        tB[sl * 33 + lane] = (aR[rep] + brv) * (1.f / N_);
    }
    __syncthreads();

    // coalesced fp16 stores: row (l*32+i), 32 s-cols
    int i  = tid >> 3;
    int sq4 = (tid & 7) * 4;
    size_t base = (size_t)(l * 32 + i) * 128 + sc * 32 + sq4;
    __half2 a01 = __floats2half2_rn(tA[(sq4 + 0) * 33 + i], tA[(sq4 + 1) * 33 + i]);
    __half2 a23 = __floats2half2_rn(tA[(sq4 + 2) * 33 + i], tA[(sq4 + 3) * 33 + i]);
    __half2 b01 = __floats2half2_rn(tB[(sq4 + 0) * 33 + i], tB[(sq4 + 1) * 33 + i]);
    __half2 b23 = __floats2half2_rn(tB[(sq4 + 2) * 33 + i], tB[(sq4 + 3) * 33 + i]);
    ((__half2*)(g_A + base))[0] = a01;
    ((__half2*)(g_A + base))[1] = a23;
    ((__half2*)(g_B + base))[0] = b01;
    ((__half2*)(g_B + base))[1] = b23;
}

// ---------------------------------------------------------------------------
// w_out transpose to fp16: g_Wt[n][ij]
// ---------------------------------------------------------------------------
__global__ void __launch_bounds__(256) wt_kernel(const float* __restrict__ wo)
{
    int idx = blockIdx.x * 256 + threadIdx.x;   // 131072
    int k = idx >> 7, n = idx & 127;
    g_Wt[(size_t)n * 1024 + k] = __float2half_rn(wo[idx]);
}

// ---------------------------------------------------------------------------
// Fused GEMM, fp16 MMA. CTA = 8 l x 8 m = 64 pairs; 8 i-chunks.
// ---------------------------------------------------------------------------
constexpr int STH  = 136;                      // half stride
constexpr int B_OFF = 0;                       // [256][STH]
constexpr int A_OFF = B_OFF + 256 * STH;       // [32][STH]
constexpr int G_OFF = A_OFF + 32 * STH;        // [64][STH]
constexpr int W_OFF = G_OFF + 64 * STH;        // 2 x [128][STH]
constexpr int WBUF  = 128 * STH;
constexpr int SMEM_FUSED = (W_OFF + 2 * WBUF) * 2;   // 165376 bytes

__global__ void __launch_bounds__(256, 1) fused_gemm_kernel(
    const float* __restrict__ pairin,
    const float* __restrict__ bo,
    float* __restrict__ outp)
{
    extern __shared__ __half smh[];
    float* smf = (float*)smh;
    uint32_t sb = smem_u32(smh);
    int tid = threadIdx.x, lane = tid & 31, w = tid >> 5;
    int bl = blockIdx.x, bm = blockIdx.y;

    auto prefetchW = [&](int c) {
        uint32_t base = sb + (uint32_t)((W_OFF + (c & 1) * WBUF) * 2);
        int row = tid >> 1;
        int sg0 = (tid & 1) * 8;
        const __half* src = g_Wt + (size_t)row * 1024 + c * 128 + sg0 * 8;
        uint32_t dst = base + (uint32_t)((row * STH + sg0 * 8) * 2);
#pragma unroll
        for (int sg = 0; sg < 8; sg++) cpa16(dst + sg * 16, src + sg * 8);
        cpa_commit();
    };
    prefetchW(0);

    // B tile: 256 rows x 128 halves
    const __half* gB = g_B + (size_t)(bm * 256) * 128;
#pragma unroll
    for (int it = 0; it < 16; it++) {
        int f = it * 256 + tid;
        int r = f >> 4, c8 = (f & 15) * 8;
        *(uint4*)(smh + B_OFF + r * STH + c8) = *(const uint4*)(gB + (size_t)r * 128 + c8);
    }

    float outAcc[4][2][4];
#pragma unroll
    for (int mt = 0; mt < 4; mt++)
#pragma unroll
        for (int nt = 0; nt < 2; nt++)
#pragma unroll
            for (int q = 0; q < 4; q++) outAcc[mt][nt][q] = 0.f;

    // ldmatrix bases
    uint32_t aAddrA = sb + (uint32_t)((A_OFF + (lane & 15) * STH + (lane >> 4) * 8) * 2);
    uint32_t bAddrA = sb + (uint32_t)((B_OFF + (w * 32 + ((lane >> 4) & 1) * 8 + (lane & 7)) * STH
                                       + ((lane >> 3) & 1) * 8) * 2);
    uint32_t aAddrB = sb + (uint32_t)((G_OFF + (lane & 15) * STH + (lane >> 4) * 8) * 2);
    uint32_t bOffB  = (uint32_t)(((w * 16 + ((lane >> 4) & 1) * 8 + (lane & 7)) * STH
                                  + ((lane >> 3) & 1) * 8) * 2);

    const __half* gA = g_A + (size_t)(bl * 256) * 128;

#pragma unroll 1
    for (int ic = 0; ic < 8; ic++) {
        __syncthreads();                 // prev phase-B reads (Gs, Ws) done
        if (ic < 7) prefetchW(ic + 1);

        // A chunk: 32 rows (l_loc*4 + di) with i = ic*4 + di
#pragma unroll
        for (int it = 0; it < 2; it++) {
            int f = it * 256 + tid;
            int r = f >> 4, c8 = (f & 15) * 8;
            int grow = (r >> 2) * 32 + ic * 4 + (r & 3);
            *(uint4*)(smh + A_OFF + r * STH + c8) =
                *(const uint4*)(gA + (size_t)grow * 128 + c8);
        }
        __syncthreads();                 // A (and B first iter) visible

        // ---- phase A: Gc[32 x 256] = A @ B^T (K=128) ----
        float accA[2][4][4];
#pragma unroll
        for (int mt = 0; mt < 2; mt++)
#pragma unroll
            for (int nt = 0; nt < 4; nt++)
#pragma unroll
                for (int q = 0; q < 4; q++) accA[mt][nt][q] = 0.f;

#pragma unroll
        for (int ks = 0; ks < 8; ks++) {
            uint32_t a[2][4], b[2][4];
#pragma unroll
            for (int mt = 0; mt < 2; mt++)
                ldsm4(a[mt][0], a[mt][1], a[mt][2], a[mt][3],
                      aAddrA + (uint32_t)((mt * 16 * STH + ks * 16) * 2));
#pragma unroll
            for (int pr = 0; pr < 2; pr++)
                ldsm4(b[pr][0], b[pr][1], b[pr][2], b[pr][3],
                      bAddrA + (uint32_t)((pr * 16 * STH + ks * 16) * 2));
#pragma unroll
            for (int mt = 0; mt < 2; mt++)
#pragma unroll
                for (int nt = 0; nt < 4; nt++)
                    mma16816(accA[mt][nt], a[mt],
                             b[nt >> 1][(nt & 1) * 2], b[nt >> 1][(nt & 1) * 2 + 1]);
        }

        // ---- store Gc -> Gs[pair][ij_local] as fp16 ----
        {
            int rB = lane >> 2, jB = (lane & 3) * 2;
#pragma unroll
            for (int mt = 0; mt < 2; mt++) {
                int r = mt * 16 + rB;
                int q = (r & 3) * 32 + jB;
                int p = (r >> 2) * 8 + w;
#pragma unroll
                for (int nt = 0; nt < 4; nt++) {
                    *(__half2*)(smh + G_OFF + p * STH + q + nt * 8) =
                        __floats2half2_rn(accA[mt][nt][0], accA[mt][nt][1]);
                    *(__half2*)(smh + G_OFF + (p + 16) * STH + q + nt * 8) =
                        __floats2half2_rn(accA[mt][nt][2], accA[mt][nt][3]);
                }
            }
        }
        if (ic < 7) { cpa_wait<1>(); } else { cpa_wait<0>(); }
        __syncthreads();                 // Gs + W buffer visible

        // ---- phase B: out += Gs[64x128] @ W[128x128]^T ----
        uint32_t sW = sb + (uint32_t)((W_OFF + (ic & 1) * WBUF) * 2) + bOffB;
#pragma unroll
        for (int ks = 0; ks < 8; ks++) {
            uint32_t a[4][4], b[4];
#pragma unroll
            for (int mt = 0; mt < 4; mt++)
                ldsm4(a[mt][0], a[mt][1], a[mt][2], a[mt][3],
                      aAddrB + (uint32_t)((mt * 16 * STH + ks * 16) * 2));
            ldsm4(b[0], b[1], b[2], b[3], sW + (uint32_t)(ks * 16 * 2));
#pragma unroll
            for (int mt = 0; mt < 4; mt++) {
                mma16816(outAcc[mt][0], a[mt], b[0], b[1]);
                mma16816(outAcc[mt][1], a[mt], b[2], b[3]);
            }
        }
    }

    // ---- epilogue: stage outAcc (f32) in B region, coalesced writes ----
    {
        int rB = lane >> 2, nB = (lane & 3) * 2;
#pragma unroll
        for (int mt = 0; mt < 4; mt++) {
            int p = mt * 16 + rB;
#pragma unroll
            for (int nt = 0; nt < 2; nt++) {
                int nc = w * 16 + nt * 8 + nB;
                *(float2*)&smf[p * 132 + nc] =
                    make_float2(outAcc[mt][nt][0], outAcc[mt][nt][1]);
                *(float2*)&smf[(p + 8) * 132 + nc] =
                    make_float2(outAcc[mt][nt][2], outAcc[mt][nt][3]);
            }
        }
    }
    __syncthreads();

#pragma unroll
    for (int it = 0; it < 8; it++) {
        int f = it * 256 + tid;
        int p = f >> 5;
        int c4 = (f & 31) * 4;
        int l = bl * 8 + (p >> 3);
        int m = bm * 8 + (p & 7);
        size_t o = ((size_t)(l * L_ + m)) * DP + c4;
        float4 v = *(float4*)&smf[p * 132 + c4];
        float4 pv = *(const float4*)&pairin[o];
        float4 bv = *(const float4*)&bo[c4];
        v.x += pv.x + bv.x; v.y += pv.y + bv.y;
        v.z += pv.z + bv.z; v.w += pv.w + bv.w;
        *(float4*)&outp[o] = v;
    }
}

// ---------------------------------------------------------------------------
// Launch
// ---------------------------------------------------------------------------
extern "C" void kernel_launch(void* const* d_in, const int* in_sizes, int n_in,
                              void* d_out, int out_size)
{
    const float* msa    = (const float*)d_in[0];
    const float* pairin = (const float*)d_in[1];
    const float* gamma  = (const float*)d_in[4];
    const float* beta   = (const float*)d_in[5];
    const float* wl     = (const float*)d_in[6];
    const float* bleft  = (const float*)d_in[7];
    const float* wr     = (const float*)d_in[8];
    const float* bright = (const float*)d_in[9];
    const float* wo     = (const float*)d_in[10];
    const float* bo     = (const float*)d_in[11];
    float* outp = (float*)d_out;

    int smem1 = (64 * WST + 32 * 256) * (int)sizeof(float);   // 99328
    cudaFuncSetAttribute(ln_proj_kernel,
                         cudaFuncAttributeMaxDynamicSharedMemorySize, smem1);
    cudaFuncSetAttribute(fused_gemm_kernel,
                         cudaFuncAttributeMaxDynamicSharedMemorySize, SMEM_FUSED);

    ln_proj_kernel<<<1024, 256, smem1>>>(msa, gamma, beta, wl, bleft, wr, bright);
    wt_kernel<<<512, 256>>>(wo);
    fused_gemm_kernel<<<dim3(32, 32), 256, SMEM_FUSED>>>(pairin, bo, outp);
}

// round 6
// speedup vs baseline: 7.0198x; 1.5044x over previous
#include <cuda_runtime.h>
#include <cuda_fp16.h>
#include <cstdint>

// Shapes (fixed)
constexpr int N_  = 128;
constexpr int L_  = 256;
constexpr int DM  = 256;
constexpr int DP  = 128;

// Device scratch (fp16)
__device__ __half g_A[8192 * 128];   // [(l*32+i)][s]
__device__ __half g_B[8192 * 128];   // [(m*32+j)][s]
__device__ __half g_Wt[DP * 1024];   // [n][ij]

// ---------------------------------------------------------------------------
// helpers
// ---------------------------------------------------------------------------
__device__ __forceinline__ uint32_t smem_u32(const void* p) {
    uint32_t a;
    asm("{ .reg .u64 t; cvta.to.shared.u64 t, %1; cvt.u32.u64 %0, t; }"
        : "=r"(a) : "l"(p));
    return a;
}
__device__ __forceinline__ void ldsm4(uint32_t& r0, uint32_t& r1,
                                      uint32_t& r2, uint32_t& r3, uint32_t a) {
    asm volatile("ldmatrix.sync.aligned.m8n8.x4.shared.b16 {%0,%1,%2,%3}, [%4];"
                 : "=r"(r0), "=r"(r1), "=r"(r2), "=r"(r3) : "r"(a));
}
__device__ __forceinline__ void mma16816(float* d, const uint32_t* a,
                                         uint32_t b0, uint32_t b1) {
    asm volatile(
        "mma.sync.aligned.m16n8k16.row.col.f32.f16.f16.f32 "
        "{%0,%1,%2,%3}, {%4,%5,%6,%7}, {%8,%9}, {%0,%1,%2,%3};"
        : "+f"(d[0]), "+f"(d[1]), "+f"(d[2]), "+f"(d[3])
        : "r"(a[0]), "r"(a[1]), "r"(a[2]), "r"(a[3]), "r"(b0), "r"(b1));
}
__device__ __forceinline__ void cpa16(uint32_t dst, const void* src) {
    asm volatile("cp.async.cg.shared.global [%0], [%1], 16;"
                 :: "r"(dst), "l"(src) : "memory");
}
__device__ __forceinline__ void cpa_commit() {
    asm volatile("cp.async.commit_group;" ::: "memory");
}
template <int N>
__device__ __forceinline__ void cpa_wait() {
    asm volatile("cp.async.wait_group %0;" :: "n"(N) : "memory");
}
__device__ __forceinline__ uint32_t pack2h(float a, float b) {
    __half2 h = __floats2half2_rn(a, b);
    return *(uint32_t*)&h;
}

// ---------------------------------------------------------------------------
// Kernel 1: LN + projections via tensor cores. One CTA per l (grid=256).
//   LN 128 rows -> X[128][264] fp16; W staged [64][264] (left | right);
//   MMA 128x64x256; coalesced block write to g_A/g_B.
// ---------------------------------------------------------------------------
constexpr int XST = 264;

__global__ void __launch_bounds__(256) ln_proj_kernel(
    const float* __restrict__ msa,
    const float* __restrict__ gamma,
    const float* __restrict__ beta,
    const float* __restrict__ wl,
    const float* __restrict__ bleft,
    const float* __restrict__ wr,
    const float* __restrict__ bright)
{
    extern __shared__ __half sh[];
    __half* Xs = sh;                    // [128][264]
    __half* Wt = sh + 128 * XST;        // [64][264]
    float*  Osm = (float*)sh;           // reuse X region: [64][132]

    int tid = threadIdx.x, lane = tid & 31, w = tid >> 5;
    int l = blockIdx.x;

    // stage Wt fp16 (coalesced global reads)
    for (int e = tid; e < 8192; e += 256) {
        int d = e >> 5, h = e & 31;
        Wt[h * XST + d]        = __float2half_rn(wl[e]);
        Wt[(h + 32) * XST + d] = __float2half_rn(wr[e]);
    }

    // per-lane gamma/beta (d = lane*8 .. +7)
    float4 ga0 = *(const float4*)&gamma[lane * 8];
    float4 ga1 = *(const float4*)&gamma[lane * 8 + 4];
    float4 be0 = *(const float4*)&beta[lane * 8];
    float4 be1 = *(const float4*)&beta[lane * 8 + 4];

    // LN: 16 rows per warp (s = w*16 + rr)
#pragma unroll 2
    for (int rr = 0; rr < 16; rr++) {
        int s = w * 16 + rr;
        const float* x = msa + ((size_t)s * L_ + l) * DM;
        float4 x0 = *(const float4*)&x[lane * 8];
        float4 x1 = *(const float4*)&x[lane * 8 + 4];
        float sum = x0.x + x0.y + x0.z + x0.w + x1.x + x1.y + x1.z + x1.w;
        float sq  = x0.x*x0.x + x0.y*x0.y + x0.z*x0.z + x0.w*x0.w
                  + x1.x*x1.x + x1.y*x1.y + x1.z*x1.z + x1.w*x1.w;
#pragma unroll
        for (int o = 16; o > 0; o >>= 1) {
            sum += __shfl_xor_sync(0xffffffffu, sum, o);
            sq  += __shfl_xor_sync(0xffffffffu, sq,  o);
        }
        float mu = sum * (1.f / DM);
        float rstd = rsqrtf(sq * (1.f / DM) - mu * mu + 1e-5f);
        float v0 = (x0.x - mu) * rstd * ga0.x + be0.x;
        float v1 = (x0.y - mu) * rstd * ga0.y + be0.y;
        float v2 = (x0.z - mu) * rstd * ga0.z + be0.z;
        float v3 = (x0.w - mu) * rstd * ga0.w + be0.w;
        float v4 = (x1.x - mu) * rstd * ga1.x + be1.x;
        float v5 = (x1.y - mu) * rstd * ga1.y + be1.y;
        float v6 = (x1.z - mu) * rstd * ga1.z + be1.z;
        float v7 = (x1.w - mu) * rstd * ga1.w + be1.w;
        uint4 pk;
        pk.x = pack2h(v0, v1); pk.y = pack2h(v2, v3);
        pk.z = pack2h(v4, v5); pk.w = pack2h(v6, v7);
        *(uint4*)&Xs[s * XST + lane * 8] = pk;
    }
    __syncthreads();

    // MMA: M=128 (s), N=64 (left|right), K=256 (d). 8 warps: 4m x 2n.
    int wm = w >> 1, wn = w & 1;
    float acc[2][4][4];
#pragma unroll
    for (int mt = 0; mt < 2; mt++)
#pragma unroll
        for (int nt = 0; nt < 4; nt++)
#pragma unroll
            for (int q = 0; q < 4; q++) acc[mt][nt][q] = 0.f;

    uint32_t sb = smem_u32(sh);
    uint32_t aAddr = sb + (uint32_t)(((wm * 32 + (lane & 15)) * XST + (lane >> 4) * 8) * 2);
    uint32_t bAddr = sb + (uint32_t)((128 * XST
                    + (wn * 32 + ((lane >> 4) & 1) * 8 + (lane & 7)) * XST
                    + ((lane >> 3) & 1) * 8) * 2);

#pragma unroll
    for (int ks = 0; ks < 16; ks++) {
        uint32_t a[2][4], b[2][4];
#pragma unroll
        for (int mt = 0; mt < 2; mt++)
            ldsm4(a[mt][0], a[mt][1], a[mt][2], a[mt][3],
                  aAddr + (uint32_t)((mt * 16 * XST + ks * 16) * 2));
#pragma unroll
        for (int n2 = 0; n2 < 2; n2++)
            ldsm4(b[n2][0], b[n2][1], b[n2][2], b[n2][3],
                  bAddr + (uint32_t)((n2 * 16 * XST + ks * 16) * 2));
#pragma unroll
        for (int mt = 0; mt < 2; mt++)
#pragma unroll
            for (int nt = 0; nt < 4; nt++)
                mma16816(acc[mt][nt], a[mt],
                         b[nt >> 1][(nt & 1) * 2], b[nt >> 1][(nt & 1) * 2 + 1]);
    }
    __syncthreads();   // X reads done; reuse as Osm

    // stage transposed: Osm[n][s]
    {
        int rB = lane >> 2, cB = (lane & 3) * 2;
#pragma unroll
        for (int mt = 0; mt < 2; mt++) {
            int r = wm * 32 + mt * 16 + rB;
#pragma unroll
            for (int nt = 0; nt < 4; nt++) {
                int c = wn * 32 + nt * 8 + cB;
                Osm[c * 132 + r]            = acc[mt][nt][0];
                Osm[(c + 1) * 132 + r]      = acc[mt][nt][1];
                Osm[c * 132 + r + 8]        = acc[mt][nt][2];
                Osm[(c + 1) * 132 + r + 8]  = acc[mt][nt][3];
            }
        }
    }
    __syncthreads();

    // coalesced fp16 block writes: thread t -> n = t>>2, s block (t&3)*32
    {
        int n = tid >> 2, s0 = (tid & 3) * 32;
        bool isL = n < 32;
        int hh = isL ? n : n - 32;
        float bias = isL ? bleft[hh] : bright[hh];
        float scale = isL ? 1.f : (1.f / 128.f);
        __half* dst = (isL ? g_A : g_B) + (size_t)(l * 32 + hh) * 128 + s0;
#pragma unroll
        for (int q = 0; q < 4; q++) {
            float4 v0 = *(float4*)&Osm[n * 132 + s0 + q * 8];
            float4 v1 = *(float4*)&Osm[n * 132 + s0 + q * 8 + 4];
            uint4 pk;
            pk.x = pack2h((v0.x + bias) * scale, (v0.y + bias) * scale);
            pk.y = pack2h((v0.z + bias) * scale, (v0.w + bias) * scale);
            pk.z = pack2h((v1.x + bias) * scale, (v1.y + bias) * scale);
            pk.w = pack2h((v1.z + bias) * scale, (v1.w + bias) * scale);
            *(uint4*)(dst + q * 8) = pk;
        }
    }
}

// ---------------------------------------------------------------------------
// w_out transpose to fp16: g_Wt[n][ij]
// ---------------------------------------------------------------------------
__global__ void __launch_bounds__(256) wt_kernel(const float* __restrict__ wo)
{
    int idx = blockIdx.x * 256 + threadIdx.x;
    int k = idx >> 7, n = idx & 127;
    g_Wt[(size_t)n * 1024 + k] = __float2half_rn(wo[idx]);
}

// ---------------------------------------------------------------------------
// Fused GEMM, fp16 MMA, fully async pipeline.
//   A double-buffered, W triple-buffered, B in prologue group, 2 syncs/ic.
// ---------------------------------------------------------------------------
constexpr int STH   = 136;
constexpr int B_OFF = 0;                        // [256][STH]
constexpr int A_OFF = 256 * STH;                // 2 x [32][STH]
constexpr int G_OFF = A_OFF + 2 * 32 * STH;     // [64][STH]
constexpr int W_OFF = G_OFF + 64 * STH;         // 3 x [128][STH]
constexpr int WBUF  = 128 * STH;
constexpr int ABUF  = 32 * STH;
constexpr int SMEM_FUSED = (W_OFF + 3 * WBUF) * 2;   // 208896 bytes

__global__ void __launch_bounds__(256, 1) fused_gemm_kernel(
    const float* __restrict__ pairin,
    const float* __restrict__ bo,
    float* __restrict__ outp)
{
    extern __shared__ __half smh[];
    float* smf = (float*)smh;
    uint32_t sb = smem_u32(smh);
    int tid = threadIdx.x, lane = tid & 31, w = tid >> 5;
    int bl = blockIdx.x, bm = blockIdx.y;

    const __half* gA = g_A + (size_t)(bl * 256) * 128;
    const __half* gB = g_B + (size_t)(bm * 256) * 128;

    auto prefetchW = [&](int c) {   // W chunk c -> slot c%3
        uint32_t base = sb + (uint32_t)((W_OFF + (c % 3) * WBUF) * 2);
        int row = tid >> 1, sg0 = (tid & 1) * 8;
        const __half* src = g_Wt + (size_t)row * 1024 + c * 128 + sg0 * 8;
        uint32_t dst = base + (uint32_t)((row * STH + sg0 * 8) * 2);
#pragma unroll
        for (int sg = 0; sg < 8; sg++) cpa16(dst + sg * 16, src + sg * 8);
    };
    auto prefetchA = [&](int c) {   // A chunk c -> slot c&1
        uint32_t base = sb + (uint32_t)((A_OFF + (c & 1) * ABUF) * 2);
#pragma unroll
        for (int it = 0; it < 2; it++) {
            int f = it * 256 + tid;
            int r = f >> 4, c8 = (f & 15) * 8;
            int grow = (r >> 2) * 32 + c * 4 + (r & 3);
            cpa16(base + (uint32_t)((r * STH + c8) * 2),
                  gA + (size_t)grow * 128 + c8);
        }
    };

    // prologue group: B + A[0] + W[0]
#pragma unroll
    for (int it = 0; it < 16; it++) {
        int f = it * 256 + tid;
        int r = f >> 4, c8 = (f & 15) * 8;
        cpa16(sb + (uint32_t)((B_OFF + r * STH + c8) * 2),
              gB + (size_t)r * 128 + c8);
    }
    prefetchA(0);
    prefetchW(0);
    cpa_commit();

    float outAcc[4][2][4];
#pragma unroll
    for (int mt = 0; mt < 4; mt++)
#pragma unroll
        for (int nt = 0; nt < 2; nt++)
#pragma unroll
            for (int q = 0; q < 4; q++) outAcc[mt][nt][q] = 0.f;

    // ldmatrix bases
    uint32_t aAddrA0 = sb + (uint32_t)((A_OFF + (lane & 15) * STH + (lane >> 4) * 8) * 2);
    uint32_t bAddrA  = sb + (uint32_t)((B_OFF + (w * 32 + ((lane >> 4) & 1) * 8 + (lane & 7)) * STH
                                        + ((lane >> 3) & 1) * 8) * 2);
    uint32_t aAddrB  = sb + (uint32_t)((G_OFF + (lane & 15) * STH + (lane >> 4) * 8) * 2);
    uint32_t bOffB   = (uint32_t)(((w * 16 + ((lane >> 4) & 1) * 8 + (lane & 7)) * STH
                                   + ((lane >> 3) & 1) * 8) * 2);

#pragma unroll 1
    for (int ic = 0; ic < 8; ic++) {
        if (ic < 7) {
            prefetchA(ic + 1);
            prefetchW(ic + 1);
            cpa_commit();
            cpa_wait<1>();
        } else {
            cpa_wait<0>();
        }
        __syncthreads();   // A[ic], W[ic] (and B first iter) visible; prev phase B done

        // ---- phase A: Gc[32 x 256] = A @ B^T (K=128) ----
        uint32_t aA = aAddrA0 + (uint32_t)((ic & 1) * ABUF * 2);
        float accA[2][4][4];
#pragma unroll
        for (int mt = 0; mt < 2; mt++)
#pragma unroll
            for (int nt = 0; nt < 4; nt++)
#pragma unroll
                for (int q = 0; q < 4; q++) accA[mt][nt][q] = 0.f;

#pragma unroll
        for (int ks = 0; ks < 8; ks++) {
            uint32_t a[2][4], b[2][4];
#pragma unroll
            for (int mt = 0; mt < 2; mt++)
                ldsm4(a[mt][0], a[mt][1], a[mt][2], a[mt][3],
                      aA + (uint32_t)((mt * 16 * STH + ks * 16) * 2));
#pragma unroll
            for (int pr = 0; pr < 2; pr++)
                ldsm4(b[pr][0], b[pr][1], b[pr][2], b[pr][3],
                      bAddrA + (uint32_t)((pr * 16 * STH + ks * 16) * 2));
#pragma unroll
            for (int mt = 0; mt < 2; mt++)
#pragma unroll
                for (int nt = 0; nt < 4; nt++)
                    mma16816(accA[mt][nt], a[mt],
                             b[nt >> 1][(nt & 1) * 2], b[nt >> 1][(nt & 1) * 2 + 1]);
        }

        // ---- store Gc -> Gs[pair][ij_local] fp16 ----
        {
            int rB = lane >> 2, jB = (lane & 3) * 2;
#pragma unroll
            for (int mt = 0; mt < 2; mt++) {
                int r = mt * 16 + rB;
                int q = (r & 3) * 32 + jB;
                int p = (r >> 2) * 8 + w;
#pragma unroll
                for (int nt = 0; nt < 4; nt++) {
                    *(uint32_t*)(smh + G_OFF + p * STH + q + nt * 8) =
                        pack2h(accA[mt][nt][0], accA[mt][nt][1]);
                    *(uint32_t*)(smh + G_OFF + (p + 16) * STH + q + nt * 8) =
                        pack2h(accA[mt][nt][2], accA[mt][nt][3]);
                }
            }
        }
        __syncthreads();   // Gs visible

        // ---- phase B: out += Gs[64x128] @ W[128x128]^T ----
        uint32_t sW = sb + (uint32_t)((W_OFF + (ic % 3) * WBUF) * 2) + bOffB;
#pragma unroll
        for (int ks = 0; ks < 8; ks++) {
            uint32_t a[4][4], b[4];
#pragma unroll
            for (int mt = 0; mt < 4; mt++)
                ldsm4(a[mt][0], a[mt][1], a[mt][2], a[mt][3],
                      aAddrB + (uint32_t)((mt * 16 * STH + ks * 16) * 2));
            ldsm4(b[0], b[1], b[2], b[3], sW + (uint32_t)(ks * 16 * 2));
#pragma unroll
            for (int mt = 0; mt < 4; mt++) {
                mma16816(outAcc[mt][0], a[mt], b[0], b[1]);
                mma16816(outAcc[mt][1], a[mt], b[2], b[3]);
            }
        }
    }

    // ---- epilogue: stage f32 in B region, coalesced writes ----
    {
        int rB = lane >> 2, nB = (lane & 3) * 2;
#pragma unroll
        for (int mt = 0; mt < 4; mt++) {
            int p = mt * 16 + rB;
#pragma unroll
            for (int nt = 0; nt < 2; nt++) {
                int nc = w * 16 + nt * 8 + nB;
                *(float2*)&smf[p * 132 + nc] =
                    make_float2(outAcc[mt][nt][0], outAcc[mt][nt][1]);
                *(float2*)&smf[(p + 8) * 132 + nc] =
                    make_float2(outAcc[mt][nt][2], outAcc[mt][nt][3]);
            }
        }
    }
    __syncthreads();

#pragma unroll
    for (int it = 0; it < 8; it++) {
        int f = it * 256 + tid;
        int p = f >> 5;
        int c4 = (f & 31) * 4;
        int l = bl * 8 + (p >> 3);
        int m = bm * 8 + (p & 7);
        size_t o = ((size_t)(l * L_ + m)) * DP + c4;
        float4 v = *(float4*)&smf[p * 132 + c4];
        float4 pv = *(const float4*)&pairin[o];
        float4 bv = *(const float4*)&bo[c4];
        v.x += pv.x + bv.x; v.y += pv.y + bv.y;
        v.z += pv.z + bv.z; v.w += pv.w + bv.w;
        *(float4*)&outp[o] = v;
    }
}

// ---------------------------------------------------------------------------
// Launch
// ---------------------------------------------------------------------------
extern "C" void kernel_launch(void* const* d_in, const int* in_sizes, int n_in,
                              void* d_out, int out_size)
{
    const float* msa    = (const float*)d_in[0];
    const float* pairin = (const float*)d_in[1];
    const float* gamma  = (const float*)d_in[4];
    const float* beta   = (const float*)d_in[5];
    const float* wl     = (const float*)d_in[6];
    const float* bleft  = (const float*)d_in[7];
    const float* wr     = (const float*)d_in[8];
    const float* bright = (const float*)d_in[9];
    const float* wo     = (const float*)d_in[10];
    const float* bo     = (const float*)d_in[11];
    float* outp = (float*)d_out;

    int smemLn = 192 * XST * 2;    // (128+64) rows * 264 halves = 101376 B
    cudaFuncSetAttribute(ln_proj_kernel,
                         cudaFuncAttributeMaxDynamicSharedMemorySize, smemLn);
    cudaFuncSetAttribute(fused_gemm_kernel,
                         cudaFuncAttributeMaxDynamicSharedMemorySize, SMEM_FUSED);

    ln_proj_kernel<<<256, 256, smemLn>>>(msa, gamma, beta, wl, bleft, wr, bright);
    wt_kernel<<<512, 256>>>(wo);
    fused_gemm_kernel<<<dim3(32, 32), 256, SMEM_FUSED>>>(pairin, bo, outp);
}